// round 2
// baseline (speedup 1.0000x reference)
#include <cuda_runtime.h>

#define B_ 2
#define L_ 4096
#define C_ 512
#define H_ 8
#define D_ 64
#define THREE_C 1536

static __device__ float g_kqv[(size_t)B_ * L_ * THREE_C];   // [B*L, 3C] : k | q | v
static __device__ float g_attn[(size_t)B_ * L_ * C_];       // [B*L, C]

// ============================================================================
// SGEMM: C[M,N] = A[M,K] @ B[K,N] (+ bias). BM=BN=64, BK=16, 256 thr, 4x4/thr
// ============================================================================
__global__ __launch_bounds__(256) void sgemm_kernel(
    const float* __restrict__ A, const float* __restrict__ Bm,
    const float* __restrict__ bias, float* __restrict__ Cm,
    int M, int N, int K)
{
    __shared__ float As[16][64];
    __shared__ float Bs[16][64];

    const int tid = threadIdx.x;
    const int bm = blockIdx.y * 64;
    const int bn = blockIdx.x * 64;
    const int tx = tid & 15, ty = tid >> 4;

    float acc[4][4];
#pragma unroll
    for (int i = 0; i < 4; ++i)
#pragma unroll
        for (int j = 0; j < 4; ++j) acc[i][j] = 0.f;

    const int ar = tid >> 2, ac = (tid & 3) << 2;   // A tile: 64 rows x 16 k
    const int br = tid >> 4, bc = (tid & 15) << 2;  // B tile: 16 k x 64 cols

    for (int k0 = 0; k0 < K; k0 += 16) {
        float4 a4 = *(const float4*)(A + (size_t)(bm + ar) * K + k0 + ac);
        As[ac + 0][ar] = a4.x; As[ac + 1][ar] = a4.y;
        As[ac + 2][ar] = a4.z; As[ac + 3][ar] = a4.w;
        *(float4*)(&Bs[br][bc]) = *(const float4*)(Bm + (size_t)(k0 + br) * N + bn + bc);
        __syncthreads();
#pragma unroll
        for (int k = 0; k < 16; ++k) {
            float4 av = *(const float4*)(&As[k][ty << 2]);
            float4 bv = *(const float4*)(&Bs[k][tx << 2]);
            float aa[4] = {av.x, av.y, av.z, av.w};
            float bb[4] = {bv.x, bv.y, bv.z, bv.w};
#pragma unroll
            for (int i = 0; i < 4; ++i)
#pragma unroll
                for (int j = 0; j < 4; ++j)
                    acc[i][j] = fmaf(aa[i], bb[j], acc[i][j]);
        }
        __syncthreads();
    }

#pragma unroll
    for (int i = 0; i < 4; ++i) {
        int row = bm + (ty << 2) + i;
        int col = bn + (tx << 2);
        float4 o;
        o.x = acc[i][0]; o.y = acc[i][1]; o.z = acc[i][2]; o.w = acc[i][3];
        if (bias) {
            o.x += bias[col]; o.y += bias[col + 1];
            o.z += bias[col + 2]; o.w += bias[col + 3];
        }
        *(float4*)(Cm + (size_t)row * N + col) = o;
    }
}

// ============================================================================
// Flash attention (fp32, exact online softmax).
// Grid: B*H*(L/64). Block: 256 thr = 8 warps. Warp w owns q-rows [8w, 8w+8).
// Lane owns columns {lane, lane+32} of both S (over K-tile) and O (over D).
// ============================================================================
#define BQ 64
#define KTILE 64
// smem: Qs[64][64] + KT[64][65] + Vs[64][64] + Ps[64][64]
#define ATTN_SMEM_FLOATS (64 * 64 + 64 * 65 + 64 * 64 + 64 * 64)
#define ATTN_SMEM_BYTES (ATTN_SMEM_FLOATS * 4)

__global__ __launch_bounds__(256) void attn_kernel(
    const float* __restrict__ kqv, float* __restrict__ attn_out)
{
    const float SCALE = 22.627416997969522f;  // sqrt(512)

    const int bid = blockIdx.x;
    const int qtile = bid & 63;          // L/BQ = 64
    const int bh = bid >> 6;
    const int h = bh & (H_ - 1);
    const int b = bh >> 3;

    const int tid = threadIdx.x;
    const int lane = tid & 31;
    const int warp = tid >> 5;
    const int q0 = warp * 8;

    extern __shared__ float sm[];
    float* Qs = sm;                  // [64][64]
    float* KT = Qs + 64 * 64;        // [64][65]  (d-major, transposed K)
    float* Vs = KT + 64 * 65;        // [64][64]
    float* Ps = Vs + 64 * 64;        // [64][64]

    const size_t row_base = (size_t)b * L_ * THREE_C;
    const float* Kp = kqv + row_base + (size_t)h * D_;            // k chunk
    const float* Qp = kqv + row_base + C_ + (size_t)h * D_;       // q chunk
    const float* Vp = kqv + row_base + 2 * C_ + (size_t)h * D_;   // v chunk

    // Load Q tile (pre-scaled): 64x64, coalesced
#pragma unroll
    for (int i = 0; i < 16; ++i) {
        int idx = tid + i * 256;
        int q = idx >> 6, d = idx & 63;
        Qs[q * 64 + d] = Qp[(size_t)(qtile * 64 + q) * THREE_C + d] * SCALE;
    }

    float m[8], rs[8], o0[8], o1[8];
#pragma unroll
    for (int q = 0; q < 8; ++q) {
        m[q] = -1e30f; rs[q] = 0.f; o0[q] = 0.f; o1[q] = 0.f;
    }

    const int dld = tid & 63;        // K-load: this thread's d
    const int jgrp = tid >> 6;       // 0..3

    for (int kt = 0; kt < L_ / KTILE; ++kt) {
        __syncthreads();   // previous iteration's smem reads done
        // Load K (transposed into KT) and V
#pragma unroll
        for (int i = 0; i < 16; ++i) {
            int j = jgrp * 16 + i;
            KT[dld * 65 + j] = Kp[(size_t)(kt * 64 + j) * THREE_C + dld];
        }
#pragma unroll
        for (int i = 0; i < 16; ++i) {
            int idx = tid + i * 256;
            int j = idx >> 6, dd = idx & 63;
            Vs[j * 64 + dd] = Vp[(size_t)(kt * 64 + j) * THREE_C + dd];
        }
        __syncthreads();

        // S = Q K^T  (each lane: 8 q-rows x 2 j-cols)
        float s0[8], s1[8];
#pragma unroll
        for (int q = 0; q < 8; ++q) { s0[q] = 0.f; s1[q] = 0.f; }

#pragma unroll
        for (int d4 = 0; d4 < 16; ++d4) {
            float k0[4], k1[4];
#pragma unroll
            for (int i = 0; i < 4; ++i) {
                k0[i] = KT[(d4 * 4 + i) * 65 + lane];
                k1[i] = KT[(d4 * 4 + i) * 65 + lane + 32];
            }
#pragma unroll
            for (int q = 0; q < 8; ++q) {
                float4 qv = *(const float4*)(&Qs[(q0 + q) * 64 + d4 * 4]);
                s0[q] += qv.x * k0[0] + qv.y * k0[1] + qv.z * k0[2] + qv.w * k0[3];
                s1[q] += qv.x * k1[0] + qv.y * k1[1] + qv.z * k1[2] + qv.w * k1[3];
            }
        }

        // Online softmax update; stash P in smem (warp-private rows)
#pragma unroll
        for (int q = 0; q < 8; ++q) {
            float tmax = fmaxf(s0[q], s1[q]);
#pragma unroll
            for (int off = 16; off; off >>= 1)
                tmax = fmaxf(tmax, __shfl_xor_sync(0xFFFFFFFFu, tmax, off));
            float mnew = fmaxf(m[q], tmax);
            float p0 = __expf(s0[q] - mnew);
            float p1 = __expf(s1[q] - mnew);
            float ps = p0 + p1;
#pragma unroll
            for (int off = 16; off; off >>= 1)
                ps += __shfl_xor_sync(0xFFFFFFFFu, ps, off);
            float corr = __expf(m[q] - mnew);
            rs[q] = rs[q] * corr + ps;
            o0[q] *= corr;
            o1[q] *= corr;
            m[q] = mnew;
            Ps[(q0 + q) * 64 + lane] = p0;
            Ps[(q0 + q) * 64 + lane + 32] = p1;
        }
        __syncwarp();

        // O += P V
#pragma unroll
        for (int j4 = 0; j4 < 16; ++j4) {
            float v0[4], v1[4];
#pragma unroll
            for (int i = 0; i < 4; ++i) {
                v0[i] = Vs[(j4 * 4 + i) * 64 + lane];
                v1[i] = Vs[(j4 * 4 + i) * 64 + lane + 32];
            }
#pragma unroll
            for (int q = 0; q < 8; ++q) {
                float4 p = *(const float4*)(&Ps[(q0 + q) * 64 + j4 * 4]);
                o0[q] += p.x * v0[0] + p.y * v0[1] + p.z * v0[2] + p.w * v0[3];
                o1[q] += p.x * v1[0] + p.y * v1[1] + p.z * v1[2] + p.w * v1[3];
            }
        }
    }

    // Epilogue: attn_out[b, l, h*64 + d] = O / rowsum
#pragma unroll
    for (int q = 0; q < 8; ++q) {
        float inv = 1.f / rs[q];
        int ql = qtile * 64 + q0 + q;
        size_t base = ((size_t)(b * L_ + ql)) * C_ + h * D_;
        attn_out[base + lane] = o0[q] * inv;
        attn_out[base + lane + 32] = o1[q] * inv;
    }
}

// ============================================================================
// Launch
// ============================================================================
extern "C" void kernel_launch(void* const* d_in, const int* in_sizes, int n_in,
                              void* d_out, int out_size)
{
    const float* x     = (const float*)d_in[0];
    const float* w_kqv = (const float*)d_in[1];
    const float* w_out = (const float*)d_in[2];
    const float* b_out = (const float*)d_in[3];
    float* out = (float*)d_out;

    float *kqv_ptr, *attn_ptr;
    cudaGetSymbolAddress((void**)&kqv_ptr, g_kqv);
    cudaGetSymbolAddress((void**)&attn_ptr, g_attn);

    cudaFuncSetAttribute(attn_kernel,
                         cudaFuncAttributeMaxDynamicSharedMemorySize,
                         ATTN_SMEM_BYTES);

    // 1) kqv = x @ w_kqv          [8192,512] x [512,1536]
    sgemm_kernel<<<dim3(THREE_C / 64, (B_ * L_) / 64), 256>>>(
        x, w_kqv, nullptr, kqv_ptr, B_ * L_, THREE_C, C_);

    // 2) attention                 grid = B*H*(L/64) = 1024
    attn_kernel<<<B_ * H_ * (L_ / BQ), 256, ATTN_SMEM_BYTES>>>(kqv_ptr, attn_ptr);

    // 3) out = attn @ w_out + b    [8192,512] x [512,512]
    sgemm_kernel<<<dim3(C_ / 64, (B_ * L_) / 64), 256>>>(
        attn_ptr, w_out, b_out, out, B_ * L_, C_, C_);
}

// round 5
// speedup vs baseline: 2.3335x; 2.3335x over previous
#include <cuda_runtime.h>
#include <cuda_fp16.h>
#include <cstdint>

#define B_ 2
#define L_ 4096
#define C_ 512
#define H_ 8
#define D_ 64
#define THREE_C 1536
#define ROWS_ (B_ * L_)

// fp16 hi/lo buffers produced by the QKV GEMM epilogue
static __device__ __half g_khi[(size_t)ROWS_ * C_];
static __device__ __half g_klo[(size_t)ROWS_ * C_];
static __device__ __half g_qhi[(size_t)ROWS_ * C_];   // pre-scaled by sqrt(512)*log2(e)
static __device__ __half g_qlo[(size_t)ROWS_ * C_];
static __device__ __half g_vhi[(size_t)ROWS_ * C_];
static __device__ __half g_vlo[(size_t)ROWS_ * C_];
static __device__ float  g_attn[(size_t)ROWS_ * C_];

#define QSCALE 32.644462410f   // sqrt(512) * log2(e)

// ============================================================================
// Small PTX helpers
// ============================================================================
__device__ __forceinline__ uint32_t smem_u32(const void* p) {
    uint32_t a;
    asm("{ .reg .u64 t; cvta.to.shared.u64 t, %1; cvt.u32.u64 %0, t; }"
        : "=r"(a) : "l"(p));
    return a;
}
#define CP16(dst, src) \
    asm volatile("cp.async.cg.shared.global [%0], [%1], 16;" :: "r"(dst), "l"(src))
#define CP_COMMIT() asm volatile("cp.async.commit_group;" ::: "memory")
#define CP_WAIT(n)  asm volatile("cp.async.wait_group %0;" :: "n"(n) : "memory")

__device__ __forceinline__ uint4 ldsm4(uint32_t addr) {
    uint4 v;
    asm volatile("ldmatrix.sync.aligned.m8n8.x4.shared.b16 {%0,%1,%2,%3}, [%4];"
                 : "=r"(v.x), "=r"(v.y), "=r"(v.z), "=r"(v.w) : "r"(addr));
    return v;
}
__device__ __forceinline__ uint4 ldsm4t(uint32_t addr) {
    uint4 v;
    asm volatile("ldmatrix.sync.aligned.m8n8.x4.trans.shared.b16 {%0,%1,%2,%3}, [%4];"
                 : "=r"(v.x), "=r"(v.y), "=r"(v.z), "=r"(v.w) : "r"(addr));
    return v;
}
__device__ __forceinline__ void mma16816(float* c, uint32_t a0, uint32_t a1,
                                         uint32_t a2, uint32_t a3,
                                         uint32_t b0, uint32_t b1) {
    asm volatile(
        "mma.sync.aligned.m16n8k16.row.col.f32.f16.f16.f32 "
        "{%0,%1,%2,%3}, {%4,%5,%6,%7}, {%8,%9}, {%0,%1,%2,%3};"
        : "+f"(c[0]), "+f"(c[1]), "+f"(c[2]), "+f"(c[3])
        : "r"(a0), "r"(a1), "r"(a2), "r"(a3), "r"(b0), "r"(b1));
}

// MUFU-free exp2: magic-number split + deg-6 Horner + exponent splice
__device__ __forceinline__ float exp2_fast(float d) {
    d = fmaxf(d, -80.f);
    float t = d + 12582912.f;                  // 1.5 * 2^23 -> round to int
    float f = d - (t - 12582912.f);            // f in [-0.5, 0.5]
    float p = 1.54035304e-4f;
    p = fmaf(p, f, 1.33335581e-3f);
    p = fmaf(p, f, 9.61812911e-3f);
    p = fmaf(p, f, 5.55041087e-2f);
    p = fmaf(p, f, 2.40226507e-1f);
    p = fmaf(p, f, 6.93147181e-1f);
    p = fmaf(p, f, 1.0f);
    return __int_as_float(__float_as_int(p) +
                          (int)((uint32_t)__float_as_int(t) << 23));
}

// ============================================================================
// Attention: mma.sync flash kernel.
// CTA = 256 thr (8 warps), q-tile 128 rows; warp w owns rows [16w,16w+16).
// K-tiles of 64; smem row stride 144B (conflict-free ldmatrix).
// ============================================================================
#define RSTR 144
#define QHI_OFF 0
#define QLO_OFF (128 * RSTR)
#define STG_OFF (2 * 128 * RSTR)
#define TSZ (64 * RSTR)          // one 64-row half tile: 9216 B
#define KHI_SUB 0
#define KLO_SUB TSZ
#define VHI_SUB (2 * TSZ)
#define VLO_SUB (3 * TSZ)
#define STG_SZ (4 * TSZ)         // 36864
#define ATTN_SMEM (STG_OFF + 2 * STG_SZ)   // 110592 B

__global__ void __launch_bounds__(256) attn_mma(float* __restrict__ attn_out)
{
    extern __shared__ char smem[];
    const uint32_t sb = smem_u32(smem);
    const int tid = threadIdx.x;
    const int lane = tid & 31;
    const int wid = tid >> 5;

    const int qt = blockIdx.x & 31;
    const int h = (blockIdx.x >> 5) & 7;
    const int b = blockIdx.x >> 8;

    const size_t bL = (size_t)b * L_;
    const int hc = h * D_;

    // ---- prologue: Q tiles (hi+lo: 2*128 rows * 8 chunks = 2048 xfers) ----
    {
        const __half* qs[2] = {g_qhi, g_qlo};
#pragma unroll
        for (int k = 0; k < 8; ++k) {
            int idx = tid + k * 256;            // 0..2047
            int buf = idx >> 10;                // 0: hi, 1: lo
            int r = (idx >> 3) & 127;
            int c = idx & 7;
            const __half* src = qs[buf] + (bL + qt * 128 + r) * C_ + hc + c * 8;
            CP16(sb + (buf ? QLO_OFF : QHI_OFF) + r * RSTR + c * 16, src);
        }
    }
    const __half* kvsrc[4] = {g_khi, g_klo, g_vhi, g_vlo};
    auto issue_stage = [&](int stage, int kt) {
        const uint32_t stg = sb + STG_OFF + stage * STG_SZ;
#pragma unroll
        for (int s = 0; s < 4; ++s) {
#pragma unroll
            for (int k = 0; k < 2; ++k) {
                int idx = tid + k * 256;        // 0..511
                int r = idx >> 3;
                int c = idx & 7;
                const __half* src = kvsrc[s] + (bL + kt * 64 + r) * C_ + hc + c * 8;
                CP16(stg + s * TSZ + r * RSTR + c * 16, src);
            }
        }
    };
    issue_stage(0, 0);
    CP_COMMIT();

    // per-thread state
    float Oc[8][4];
#pragma unroll
    for (int nb = 0; nb < 8; ++nb)
#pragma unroll
        for (int j = 0; j < 4; ++j) Oc[nb][j] = 0.f;
    float m0 = -1e30f, m1 = -1e30f, rs0 = 0.f, rs1 = 0.f;

    const int qr0 = wid * 16;
    const uint32_t q_row_off =
        (uint32_t)((qr0 + (lane & 7) + ((lane >> 3) & 1) * 8) * RSTR + (lane >> 4) * 16);

    for (int kt = 0; kt < L_ / 64; ++kt) {
        if (kt + 1 < L_ / 64) {
            issue_stage((kt + 1) & 1, kt + 1);
            CP_COMMIT();
            CP_WAIT(1);
        } else {
            CP_WAIT(0);
        }
        __syncthreads();

        const uint32_t stg = sb + STG_OFF + (kt & 1) * STG_SZ;

        // ---------- S = Q K^T (3 fp16 chains, fp32 accum) ----------
        float Sc[8][4];
#pragma unroll
        for (int nb = 0; nb < 8; ++nb)
#pragma unroll
            for (int j = 0; j < 4; ++j) Sc[nb][j] = 0.f;

#pragma unroll
        for (int chain = 0; chain < 3; ++chain) {
            const uint32_t qbase = sb + (chain == 2 ? QLO_OFF : QHI_OFF) + q_row_off;
            const uint32_t kbase = stg + (chain == 1 ? KLO_SUB : KHI_SUB);
            uint4 qf[4];
#pragma unroll
            for (int kb = 0; kb < 4; ++kb)
                qf[kb] = ldsm4(qbase + kb * 32);
            const uint32_t krow = kbase + (uint32_t)(((lane & 7)) * RSTR + (lane >> 3) * 16);
#pragma unroll
            for (int nb = 0; nb < 8; ++nb) {
                const uint32_t ka = krow + nb * 8 * RSTR;
#pragma unroll
                for (int kbp = 0; kbp < 2; ++kbp) {
                    uint4 bb = ldsm4(ka + kbp * 64);
                    mma16816(Sc[nb], qf[2 * kbp].x, qf[2 * kbp].y,
                             qf[2 * kbp].z, qf[2 * kbp].w, bb.x, bb.y);
                    mma16816(Sc[nb], qf[2 * kbp + 1].x, qf[2 * kbp + 1].y,
                             qf[2 * kbp + 1].z, qf[2 * kbp + 1].w, bb.z, bb.w);
                }
            }
        }

        // ---------- online softmax (log2 domain, MUFU-free) ----------
        float t0 = -1e30f, t1 = -1e30f;
#pragma unroll
        for (int nb = 0; nb < 8; ++nb) {
            t0 = fmaxf(t0, fmaxf(Sc[nb][0], Sc[nb][1]));
            t1 = fmaxf(t1, fmaxf(Sc[nb][2], Sc[nb][3]));
        }
        t0 = fmaxf(t0, __shfl_xor_sync(0xFFFFFFFFu, t0, 1));
        t0 = fmaxf(t0, __shfl_xor_sync(0xFFFFFFFFu, t0, 2));
        t1 = fmaxf(t1, __shfl_xor_sync(0xFFFFFFFFu, t1, 1));
        t1 = fmaxf(t1, __shfl_xor_sync(0xFFFFFFFFu, t1, 2));
        const float mn0 = fmaxf(m0, t0), mn1 = fmaxf(m1, t1);
        const float corr0 = exp2_fast(m0 - mn0), corr1 = exp2_fast(m1 - mn1);
        m0 = mn0; m1 = mn1;

        uint32_t pA[4][4];
        float ps0 = 0.f, ps1 = 0.f;
#pragma unroll
        for (int nb = 0; nb < 8; ++nb) {
            float p00 = exp2_fast(Sc[nb][0] - m0);
            float p01 = exp2_fast(Sc[nb][1] - m0);
            float p10 = exp2_fast(Sc[nb][2] - m1);
            float p11 = exp2_fast(Sc[nb][3] - m1);
            // round to fp16 FIRST; accumulate rowsum from the rounded values so
            // numerator (P_hat @ V) and denominator share the same rounding
            __half2 hlo = __floats2half2_rn(p00, p01);
            __half2 hhi = __floats2half2_rn(p10, p11);
            float2 flo = __half22float2(hlo);
            float2 fhi = __half22float2(hhi);
            ps0 += flo.x + flo.y;
            ps1 += fhi.x + fhi.y;
            uint32_t lo2 = *reinterpret_cast<uint32_t*>(&hlo);
            uint32_t hi2 = *reinterpret_cast<uint32_t*>(&hhi);
            if (nb & 1) { pA[nb >> 1][2] = lo2; pA[nb >> 1][3] = hi2; }
            else        { pA[nb >> 1][0] = lo2; pA[nb >> 1][1] = hi2; }
        }
        ps0 += __shfl_xor_sync(0xFFFFFFFFu, ps0, 1);
        ps0 += __shfl_xor_sync(0xFFFFFFFFu, ps0, 2);
        ps1 += __shfl_xor_sync(0xFFFFFFFFu, ps1, 1);
        ps1 += __shfl_xor_sync(0xFFFFFFFFu, ps1, 2);
        rs0 = rs0 * corr0 + ps0;
        rs1 = rs1 * corr1 + ps1;
#pragma unroll
        for (int nb = 0; nb < 8; ++nb) {
            Oc[nb][0] *= corr0; Oc[nb][1] *= corr0;
            Oc[nb][2] *= corr1; Oc[nb][3] *= corr1;
        }

        // ---------- O += P V (2 chains: Vhi, Vlo) ----------
#pragma unroll
        for (int chain = 0; chain < 2; ++chain) {
            const uint32_t vbase = stg + (chain ? VLO_SUB : VHI_SUB) + lane * RSTR;
#pragma unroll
            for (int nb = 0; nb < 8; ++nb) {
#pragma unroll
                for (int kbp = 0; kbp < 2; ++kbp) {
                    uint4 vv = ldsm4t(vbase + kbp * 32 * RSTR + nb * 16);
                    mma16816(Oc[nb], pA[2 * kbp][0], pA[2 * kbp][1],
                             pA[2 * kbp][2], pA[2 * kbp][3], vv.x, vv.y);
                    mma16816(Oc[nb], pA[2 * kbp + 1][0], pA[2 * kbp + 1][1],
                             pA[2 * kbp + 1][2], pA[2 * kbp + 1][3], vv.z, vv.w);
                }
            }
        }
        __syncthreads();
    }

    // ---------- epilogue ----------
    const float inv0 = 1.f / rs0, inv1 = 1.f / rs1;
    const int r = qt * 128 + qr0 + (lane >> 2);
    const int colb = hc + 2 * (lane & 3);
#pragma unroll
    for (int nb = 0; nb < 8; ++nb) {
        float2 v0 = make_float2(Oc[nb][0] * inv0, Oc[nb][1] * inv0);
        float2 v1 = make_float2(Oc[nb][2] * inv1, Oc[nb][3] * inv1);
        *(float2*)(attn_out + (bL + r) * C_ + colb + nb * 8) = v0;
        *(float2*)(attn_out + (bL + r + 8) * C_ + colb + nb * 8) = v1;
    }
}

// ============================================================================
// SGEMM (fp32 roofline). MODE 0: fp32 out + bias. MODE 1: split-fp16 epilogue.
// ============================================================================
template <int MODE>
__global__ __launch_bounds__(256) void sgemm_kernel(
    const float* __restrict__ A, const float* __restrict__ Bm,
    const float* __restrict__ bias, float* __restrict__ Cm,
    int M, int N, int K)
{
    __shared__ float As[16][64];
    __shared__ float Bs[16][64];

    const int tid = threadIdx.x;
    const int bm = blockIdx.y * 64;
    const int bn = blockIdx.x * 64;
    const int tx = tid & 15, ty = tid >> 4;

    float acc[4][4];
#pragma unroll
    for (int i = 0; i < 4; ++i)
#pragma unroll
        for (int j = 0; j < 4; ++j) acc[i][j] = 0.f;

    const int ar = tid >> 2, ac = (tid & 3) << 2;
    const int br = tid >> 4, bc = (tid & 15) << 2;

    for (int k0 = 0; k0 < K; k0 += 16) {
        float4 a4 = *(const float4*)(A + (size_t)(bm + ar) * K + k0 + ac);
        As[ac + 0][ar] = a4.x; As[ac + 1][ar] = a4.y;
        As[ac + 2][ar] = a4.z; As[ac + 3][ar] = a4.w;
        *(float4*)(&Bs[br][bc]) = *(const float4*)(Bm + (size_t)(k0 + br) * N + bn + bc);
        __syncthreads();
#pragma unroll
        for (int k = 0; k < 16; ++k) {
            float4 av = *(const float4*)(&As[k][ty << 2]);
            float4 bv = *(const float4*)(&Bs[k][tx << 2]);
            float aa[4] = {av.x, av.y, av.z, av.w};
            float bb[4] = {bv.x, bv.y, bv.z, bv.w};
#pragma unroll
            for (int i = 0; i < 4; ++i)
#pragma unroll
                for (int j = 0; j < 4; ++j)
                    acc[i][j] = fmaf(aa[i], bb[j], acc[i][j]);
        }
        __syncthreads();
    }

    if (MODE == 0) {
#pragma unroll
        for (int i = 0; i < 4; ++i) {
            int row = bm + (ty << 2) + i;
            int col = bn + (tx << 2);
            float4 o;
            o.x = acc[i][0] + bias[col];
            o.y = acc[i][1] + bias[col + 1];
            o.z = acc[i][2] + bias[col + 2];
            o.w = acc[i][3] + bias[col + 3];
            *(float4*)(Cm + (size_t)row * N + col) = o;
        }
    } else {
        const int chunk = bn >> 9;              // 0:k 1:q 2:v
        __half* hiB = chunk == 0 ? g_khi : (chunk == 1 ? g_qhi : g_vhi);
        __half* loB = chunk == 0 ? g_klo : (chunk == 1 ? g_qlo : g_vlo);
        const float sc = (chunk == 1) ? QSCALE : 1.f;
#pragma unroll
        for (int i = 0; i < 4; ++i) {
            int row = bm + (ty << 2) + i;
            int col = (bn & 511) + (tx << 2);
            size_t base = (size_t)row * C_ + col;
            __half hv[4], lv[4];
#pragma unroll
            for (int j = 0; j < 4; ++j) {
                float v = acc[i][j] * sc;
                __half hh = __float2half_rn(v);
                hv[j] = hh;
                lv[j] = __float2half_rn(v - __half2float(hh));
            }
            ((__half2*)(hiB + base))[0] = __halves2half2(hv[0], hv[1]);
            ((__half2*)(hiB + base))[1] = __halves2half2(hv[2], hv[3]);
            ((__half2*)(loB + base))[0] = __halves2half2(lv[0], lv[1]);
            ((__half2*)(loB + base))[1] = __halves2half2(lv[2], lv[3]);
        }
    }
}

// ============================================================================
// Launch
// ============================================================================
extern "C" void kernel_launch(void* const* d_in, const int* in_sizes, int n_in,
                              void* d_out, int out_size)
{
    const float* x     = (const float*)d_in[0];
    const float* w_kqv = (const float*)d_in[1];
    const float* w_out = (const float*)d_in[2];
    const float* b_out = (const float*)d_in[3];
    float* out = (float*)d_out;

    float* attn_ptr;
    cudaGetSymbolAddress((void**)&attn_ptr, g_attn);

    cudaFuncSetAttribute(attn_mma,
                         cudaFuncAttributeMaxDynamicSharedMemorySize, ATTN_SMEM);

    // 1) QKV GEMM with split-fp16 epilogue (writes g_{k,q,v}{hi,lo})
    sgemm_kernel<1><<<dim3(THREE_C / 64, ROWS_ / 64), 256>>>(
        x, w_kqv, nullptr, nullptr, ROWS_, THREE_C, C_);

    // 2) attention (mma.sync flash, log2-domain softmax)
    attn_mma<<<B_ * H_ * (L_ / 128), 256, ATTN_SMEM>>>(attn_ptr);

    // 3) out = attn @ w_out + b
    sgemm_kernel<0><<<dim3(C_ / 64, ROWS_ / 64), 256>>>(
        attn_ptr, w_out, b_out, out, ROWS_, C_, C_);
}

// round 6
// speedup vs baseline: 2.9906x; 1.2816x over previous
#include <cuda_runtime.h>
#include <cuda_fp16.h>
#include <cstdint>

#define B_ 2
#define L_ 4096
#define C_ 512
#define H_ 8
#define D_ 64
#define THREE_C 1536
#define ROWS_ (B_ * L_)

// fp16 hi/lo split buffers
static __device__ __half g_xhi[(size_t)ROWS_ * C_];
static __device__ __half g_xlo[(size_t)ROWS_ * C_];
static __device__ __half g_wkhi[(size_t)C_ * THREE_C];
static __device__ __half g_wklo[(size_t)C_ * THREE_C];
static __device__ __half g_wohi[(size_t)C_ * C_];
static __device__ __half g_wolo[(size_t)C_ * C_];
static __device__ __half g_khi[(size_t)ROWS_ * C_];
static __device__ __half g_klo[(size_t)ROWS_ * C_];
static __device__ __half g_qhi[(size_t)ROWS_ * C_];   // pre-scaled by sqrt(512)*log2(e)
static __device__ __half g_qlo[(size_t)ROWS_ * C_];
static __device__ __half g_vhi[(size_t)ROWS_ * C_];
static __device__ __half g_vlo[(size_t)ROWS_ * C_];
static __device__ __half g_ahi[(size_t)ROWS_ * C_];   // attention output hi/lo
static __device__ __half g_alo[(size_t)ROWS_ * C_];

#define QSCALE 32.644462410f   // sqrt(512) * log2(e)

// ============================================================================
// Small PTX helpers
// ============================================================================
__device__ __forceinline__ uint32_t smem_u32(const void* p) {
    uint32_t a;
    asm("{ .reg .u64 t; cvta.to.shared.u64 t, %1; cvt.u32.u64 %0, t; }"
        : "=r"(a) : "l"(p));
    return a;
}
#define CP16(dst, src) \
    asm volatile("cp.async.cg.shared.global [%0], [%1], 16;" :: "r"(dst), "l"(src))
#define CP_COMMIT() asm volatile("cp.async.commit_group;" ::: "memory")
#define CP_WAIT(n)  asm volatile("cp.async.wait_group %0;" :: "n"(n) : "memory")

__device__ __forceinline__ uint4 ldsm4(uint32_t addr) {
    uint4 v;
    asm volatile("ldmatrix.sync.aligned.m8n8.x4.shared.b16 {%0,%1,%2,%3}, [%4];"
                 : "=r"(v.x), "=r"(v.y), "=r"(v.z), "=r"(v.w) : "r"(addr));
    return v;
}
__device__ __forceinline__ uint4 ldsm4t(uint32_t addr) {
    uint4 v;
    asm volatile("ldmatrix.sync.aligned.m8n8.x4.trans.shared.b16 {%0,%1,%2,%3}, [%4];"
                 : "=r"(v.x), "=r"(v.y), "=r"(v.z), "=r"(v.w) : "r"(addr));
    return v;
}
__device__ __forceinline__ void mma16816(float* c, uint32_t a0, uint32_t a1,
                                         uint32_t a2, uint32_t a3,
                                         uint32_t b0, uint32_t b1) {
    asm volatile(
        "mma.sync.aligned.m16n8k16.row.col.f32.f16.f16.f32 "
        "{%0,%1,%2,%3}, {%4,%5,%6,%7}, {%8,%9}, {%0,%1,%2,%3};"
        : "+f"(c[0]), "+f"(c[1]), "+f"(c[2]), "+f"(c[3])
        : "r"(a0), "r"(a1), "r"(a2), "r"(a3), "r"(b0), "r"(b1));
}

// MUFU-free exp2
__device__ __forceinline__ float exp2_fast(float d) {
    d = fmaxf(d, -80.f);
    float t = d + 12582912.f;
    float f = d - (t - 12582912.f);
    float p = 1.54035304e-4f;
    p = fmaf(p, f, 1.33335581e-3f);
    p = fmaf(p, f, 9.61812911e-3f);
    p = fmaf(p, f, 5.55041087e-2f);
    p = fmaf(p, f, 2.40226507e-1f);
    p = fmaf(p, f, 6.93147181e-1f);
    p = fmaf(p, f, 1.0f);
    return __int_as_float(__float_as_int(p) +
                          (int)((uint32_t)__float_as_int(t) << 23));
}

// ============================================================================
// fp32 -> fp16 hi/lo split (vectorized, grid-stride)
// ============================================================================
__global__ void split_kernel(const float4* __restrict__ src,
                             uint2* __restrict__ hi, uint2* __restrict__ lo,
                             int n4)
{
    for (int i = blockIdx.x * blockDim.x + threadIdx.x; i < n4;
         i += gridDim.x * blockDim.x) {
        float4 v = src[i];
        __half2 h0 = __floats2half2_rn(v.x, v.y);
        __half2 h1 = __floats2half2_rn(v.z, v.w);
        float2 f0 = __half22float2(h0), f1 = __half22float2(h1);
        __half2 l0 = __floats2half2_rn(v.x - f0.x, v.y - f0.y);
        __half2 l1 = __floats2half2_rn(v.z - f1.x, v.w - f1.y);
        hi[i] = make_uint2(*(uint32_t*)&h0, *(uint32_t*)&h1);
        lo[i] = make_uint2(*(uint32_t*)&l0, *(uint32_t*)&l1);
    }
}

// ============================================================================
// HMMA GEMM: C[8192, N] = A[8192, 512] @ B[512, N], 3-chain fp16 split.
// BM=128, BN=64, BK=64. 8 warps; warp w owns rows [16w, 16w+16).
// A smem [m][k] (ldsm4, Q pattern), B smem [k][n] (ldsm4t, V pattern).
// MODE 0: fp32 out + bias. MODE 1: kqv split-fp16 epilogue (QSCALE on q).
// ============================================================================
#define RSTR 144
#define GA_HI 0
#define GA_LO (128 * RSTR)
#define GB_HI (2 * 128 * RSTR)
#define GB_LO (2 * 128 * RSTR + 64 * RSTR)
#define G_STG_SZ (2 * 128 * RSTR + 2 * 64 * RSTR)   // 55296
#define G_SMEM (2 * G_STG_SZ)                        // 110592

template <int MODE>
__global__ void __launch_bounds__(256) hgemm(
    const __half* __restrict__ Ahi, const __half* __restrict__ Alo,
    const __half* __restrict__ Bhi, const __half* __restrict__ Blo,
    const float* __restrict__ bias, float* __restrict__ out, int N)
{
    extern __shared__ char smem[];
    const uint32_t sb = smem_u32(smem);
    const int tid = threadIdx.x;
    const int lane = tid & 31;
    const int wid = tid >> 5;
    const int bm = blockIdx.y * 128;
    const int bn = blockIdx.x * 64;

    auto issue_stage = [&](int stage, int k0) {
        const uint32_t stg = sb + stage * G_STG_SZ;
        // A tiles: 128 rows x 64 halves (hi + lo)
#pragma unroll
        for (int k = 0; k < 4; ++k) {
            int idx = tid + k * 256;            // 0..1023
            int r = idx >> 3, c = idx & 7;
            CP16(stg + GA_HI + r * RSTR + c * 16,
                 Ahi + (size_t)(bm + r) * C_ + k0 + c * 8);
            CP16(stg + GA_LO + r * RSTR + c * 16,
                 Alo + (size_t)(bm + r) * C_ + k0 + c * 8);
        }
        // B tiles: 64 k-rows x 64 halves (hi + lo)
#pragma unroll
        for (int k = 0; k < 2; ++k) {
            int idx = tid + k * 256;            // 0..511
            int r = idx >> 3, c = idx & 7;
            CP16(stg + GB_HI + r * RSTR + c * 16,
                 Bhi + (size_t)(k0 + r) * N + bn + c * 8);
            CP16(stg + GB_LO + r * RSTR + c * 16,
                 Blo + (size_t)(k0 + r) * N + bn + c * 8);
        }
    };
    issue_stage(0, 0);
    CP_COMMIT();

    float acc[8][4];
#pragma unroll
    for (int nb = 0; nb < 8; ++nb)
#pragma unroll
        for (int j = 0; j < 4; ++j) acc[nb][j] = 0.f;

    const int qr0 = wid * 16;
    const uint32_t a_row_off =
        (uint32_t)((qr0 + (lane & 7) + ((lane >> 3) & 1) * 8) * RSTR + (lane >> 4) * 16);

    for (int kt = 0; kt < 8; ++kt) {
        if (kt + 1 < 8) {
            issue_stage((kt + 1) & 1, (kt + 1) * 64);
            CP_COMMIT();
            CP_WAIT(1);
        } else {
            CP_WAIT(0);
        }
        __syncthreads();

        const uint32_t stg = sb + (kt & 1) * G_STG_SZ;
#pragma unroll
        for (int chain = 0; chain < 3; ++chain) {
            const uint32_t abase = stg + (chain == 2 ? GA_LO : GA_HI) + a_row_off;
            const uint32_t bbase = stg + (chain == 1 ? GB_LO : GB_HI) + lane * RSTR;
            uint4 af[4];
#pragma unroll
            for (int kb = 0; kb < 4; ++kb)
                af[kb] = ldsm4(abase + kb * 32);
#pragma unroll
            for (int nb = 0; nb < 8; ++nb) {
#pragma unroll
                for (int kbp = 0; kbp < 2; ++kbp) {
                    uint4 bb = ldsm4t(bbase + kbp * 32 * RSTR + nb * 16);
                    mma16816(acc[nb], af[2 * kbp].x, af[2 * kbp].y,
                             af[2 * kbp].z, af[2 * kbp].w, bb.x, bb.y);
                    mma16816(acc[nb], af[2 * kbp + 1].x, af[2 * kbp + 1].y,
                             af[2 * kbp + 1].z, af[2 * kbp + 1].w, bb.z, bb.w);
                }
            }
        }
        __syncthreads();
    }

    // ---------------- epilogue ----------------
    const int row0 = bm + qr0 + (lane >> 2);
    if (MODE == 0) {
#pragma unroll
        for (int nb = 0; nb < 8; ++nb) {
            int col = bn + nb * 8 + 2 * (lane & 3);
            float2 b2 = *(const float2*)(bias + col);
            *(float2*)(out + (size_t)row0 * C_ + col) =
                make_float2(acc[nb][0] + b2.x, acc[nb][1] + b2.y);
            *(float2*)(out + (size_t)(row0 + 8) * C_ + col) =
                make_float2(acc[nb][2] + b2.x, acc[nb][3] + b2.y);
        }
    } else {
        const int chunk = bn >> 9;              // 0:k 1:q 2:v
        __half* hiB = chunk == 0 ? g_khi : (chunk == 1 ? g_qhi : g_vhi);
        __half* loB = chunk == 0 ? g_klo : (chunk == 1 ? g_qlo : g_vlo);
        const float sc = (chunk == 1) ? QSCALE : 1.f;
#pragma unroll
        for (int nb = 0; nb < 8; ++nb) {
            int lc = (bn & 511) + nb * 8 + 2 * (lane & 3);
#pragma unroll
            for (int half_ : {0, 1}) {
                int row = row0 + half_ * 8;
                float v0 = acc[nb][2 * half_] * sc;
                float v1 = acc[nb][2 * half_ + 1] * sc;
                __half2 h = __floats2half2_rn(v0, v1);
                float2 hf = __half22float2(h);
                __half2 l = __floats2half2_rn(v0 - hf.x, v1 - hf.y);
                *(uint32_t*)(hiB + (size_t)row * C_ + lc) = *(uint32_t*)&h;
                *(uint32_t*)(loB + (size_t)row * C_ + lc) = *(uint32_t*)&l;
            }
        }
    }
}

// ============================================================================
// Attention: mma.sync flash kernel (validated R5) — epilogue now emits fp16 hi/lo
// ============================================================================
#define QHI_OFF 0
#define QLO_OFF (128 * RSTR)
#define STG_OFF (2 * 128 * RSTR)
#define TSZ (64 * RSTR)
#define KHI_SUB 0
#define KLO_SUB TSZ
#define VHI_SUB (2 * TSZ)
#define VLO_SUB (3 * TSZ)
#define STG_SZ (4 * TSZ)
#define ATTN_SMEM (STG_OFF + 2 * STG_SZ)   // 110592 B

__global__ void __launch_bounds__(256) attn_mma()
{
    extern __shared__ char smem[];
    const uint32_t sb = smem_u32(smem);
    const int tid = threadIdx.x;
    const int lane = tid & 31;
    const int wid = tid >> 5;

    const int qt = blockIdx.x & 31;
    const int h = (blockIdx.x >> 5) & 7;
    const int b = blockIdx.x >> 8;

    const size_t bL = (size_t)b * L_;
    const int hc = h * D_;

    {
        const __half* qs[2] = {g_qhi, g_qlo};
#pragma unroll
        for (int k = 0; k < 8; ++k) {
            int idx = tid + k * 256;
            int buf = idx >> 10;
            int r = (idx >> 3) & 127;
            int c = idx & 7;
            const __half* src = qs[buf] + (bL + qt * 128 + r) * C_ + hc + c * 8;
            CP16(sb + (buf ? QLO_OFF : QHI_OFF) + r * RSTR + c * 16, src);
        }
    }
    const __half* kvsrc[4] = {g_khi, g_klo, g_vhi, g_vlo};
    auto issue_stage = [&](int stage, int kt) {
        const uint32_t stg = sb + STG_OFF + stage * STG_SZ;
#pragma unroll
        for (int s = 0; s < 4; ++s) {
#pragma unroll
            for (int k = 0; k < 2; ++k) {
                int idx = tid + k * 256;
                int r = idx >> 3;
                int c = idx & 7;
                const __half* src = kvsrc[s] + (bL + kt * 64 + r) * C_ + hc + c * 8;
                CP16(stg + s * TSZ + r * RSTR + c * 16, src);
            }
        }
    };
    issue_stage(0, 0);
    CP_COMMIT();

    float Oc[8][4];
#pragma unroll
    for (int nb = 0; nb < 8; ++nb)
#pragma unroll
        for (int j = 0; j < 4; ++j) Oc[nb][j] = 0.f;
    float m0 = -1e30f, m1 = -1e30f, rs0 = 0.f, rs1 = 0.f;

    const int qr0 = wid * 16;
    const uint32_t q_row_off =
        (uint32_t)((qr0 + (lane & 7) + ((lane >> 3) & 1) * 8) * RSTR + (lane >> 4) * 16);

    for (int kt = 0; kt < L_ / 64; ++kt) {
        if (kt + 1 < L_ / 64) {
            issue_stage((kt + 1) & 1, kt + 1);
            CP_COMMIT();
            CP_WAIT(1);
        } else {
            CP_WAIT(0);
        }
        __syncthreads();

        const uint32_t stg = sb + STG_OFF + (kt & 1) * STG_SZ;

        float Sc[8][4];
#pragma unroll
        for (int nb = 0; nb < 8; ++nb)
#pragma unroll
            for (int j = 0; j < 4; ++j) Sc[nb][j] = 0.f;

#pragma unroll
        for (int chain = 0; chain < 3; ++chain) {
            const uint32_t qbase = sb + (chain == 2 ? QLO_OFF : QHI_OFF) + q_row_off;
            const uint32_t kbase = stg + (chain == 1 ? KLO_SUB : KHI_SUB);
            uint4 qf[4];
#pragma unroll
            for (int kb = 0; kb < 4; ++kb)
                qf[kb] = ldsm4(qbase + kb * 32);
            const uint32_t krow = kbase + (uint32_t)(((lane & 7)) * RSTR + (lane >> 3) * 16);
#pragma unroll
            for (int nb = 0; nb < 8; ++nb) {
                const uint32_t ka = krow + nb * 8 * RSTR;
#pragma unroll
                for (int kbp = 0; kbp < 2; ++kbp) {
                    uint4 bb = ldsm4(ka + kbp * 64);
                    mma16816(Sc[nb], qf[2 * kbp].x, qf[2 * kbp].y,
                             qf[2 * kbp].z, qf[2 * kbp].w, bb.x, bb.y);
                    mma16816(Sc[nb], qf[2 * kbp + 1].x, qf[2 * kbp + 1].y,
                             qf[2 * kbp + 1].z, qf[2 * kbp + 1].w, bb.z, bb.w);
                }
            }
        }

        float t0 = -1e30f, t1 = -1e30f;
#pragma unroll
        for (int nb = 0; nb < 8; ++nb) {
            t0 = fmaxf(t0, fmaxf(Sc[nb][0], Sc[nb][1]));
            t1 = fmaxf(t1, fmaxf(Sc[nb][2], Sc[nb][3]));
        }
        t0 = fmaxf(t0, __shfl_xor_sync(0xFFFFFFFFu, t0, 1));
        t0 = fmaxf(t0, __shfl_xor_sync(0xFFFFFFFFu, t0, 2));
        t1 = fmaxf(t1, __shfl_xor_sync(0xFFFFFFFFu, t1, 1));
        t1 = fmaxf(t1, __shfl_xor_sync(0xFFFFFFFFu, t1, 2));
        const float mn0 = fmaxf(m0, t0), mn1 = fmaxf(m1, t1);
        const float corr0 = exp2_fast(m0 - mn0), corr1 = exp2_fast(m1 - mn1);
        m0 = mn0; m1 = mn1;

        uint32_t pA[4][4];
        float ps0 = 0.f, ps1 = 0.f;
#pragma unroll
        for (int nb = 0; nb < 8; ++nb) {
            float p00 = exp2_fast(Sc[nb][0] - m0);
            float p01 = exp2_fast(Sc[nb][1] - m0);
            float p10 = exp2_fast(Sc[nb][2] - m1);
            float p11 = exp2_fast(Sc[nb][3] - m1);
            __half2 hlo = __floats2half2_rn(p00, p01);
            __half2 hhi = __floats2half2_rn(p10, p11);
            float2 flo = __half22float2(hlo);
            float2 fhi = __half22float2(hhi);
            ps0 += flo.x + flo.y;
            ps1 += fhi.x + fhi.y;
            uint32_t lo2 = *reinterpret_cast<uint32_t*>(&hlo);
            uint32_t hi2 = *reinterpret_cast<uint32_t*>(&hhi);
            if (nb & 1) { pA[nb >> 1][2] = lo2; pA[nb >> 1][3] = hi2; }
            else        { pA[nb >> 1][0] = lo2; pA[nb >> 1][1] = hi2; }
        }
        ps0 += __shfl_xor_sync(0xFFFFFFFFu, ps0, 1);
        ps0 += __shfl_xor_sync(0xFFFFFFFFu, ps0, 2);
        ps1 += __shfl_xor_sync(0xFFFFFFFFu, ps1, 1);
        ps1 += __shfl_xor_sync(0xFFFFFFFFu, ps1, 2);
        rs0 = rs0 * corr0 + ps0;
        rs1 = rs1 * corr1 + ps1;
#pragma unroll
        for (int nb = 0; nb < 8; ++nb) {
            Oc[nb][0] *= corr0; Oc[nb][1] *= corr0;
            Oc[nb][2] *= corr1; Oc[nb][3] *= corr1;
        }

#pragma unroll
        for (int chain = 0; chain < 2; ++chain) {
            const uint32_t vbase = stg + (chain ? VLO_SUB : VHI_SUB) + lane * RSTR;
#pragma unroll
            for (int nb = 0; nb < 8; ++nb) {
#pragma unroll
                for (int kbp = 0; kbp < 2; ++kbp) {
                    uint4 vv = ldsm4t(vbase + kbp * 32 * RSTR + nb * 16);
                    mma16816(Oc[nb], pA[2 * kbp][0], pA[2 * kbp][1],
                             pA[2 * kbp][2], pA[2 * kbp][3], vv.x, vv.y);
                    mma16816(Oc[nb], pA[2 * kbp + 1][0], pA[2 * kbp + 1][1],
                             pA[2 * kbp + 1][2], pA[2 * kbp + 1][3], vv.z, vv.w);
                }
            }
        }
        __syncthreads();
    }

    // ---------- epilogue: write O as fp16 hi/lo ----------
    const float inv0 = 1.f / rs0, inv1 = 1.f / rs1;
    const int r = qt * 128 + qr0 + (lane >> 2);
    const int colb = hc + 2 * (lane & 3);
#pragma unroll
    for (int nb = 0; nb < 8; ++nb) {
        float a0 = Oc[nb][0] * inv0, a1 = Oc[nb][1] * inv0;
        float b0 = Oc[nb][2] * inv1, b1 = Oc[nb][3] * inv1;
        __half2 h0 = __floats2half2_rn(a0, a1);
        __half2 h1 = __floats2half2_rn(b0, b1);
        float2 f0 = __half22float2(h0), f1 = __half22float2(h1);
        __half2 l0 = __floats2half2_rn(a0 - f0.x, a1 - f0.y);
        __half2 l1 = __floats2half2_rn(b0 - f1.x, b1 - f1.y);
        size_t base0 = (bL + r) * C_ + colb + nb * 8;
        size_t base1 = (bL + r + 8) * C_ + colb + nb * 8;
        *(uint32_t*)(g_ahi + base0) = *(uint32_t*)&h0;
        *(uint32_t*)(g_alo + base0) = *(uint32_t*)&l0;
        *(uint32_t*)(g_ahi + base1) = *(uint32_t*)&h1;
        *(uint32_t*)(g_alo + base1) = *(uint32_t*)&l1;
    }
}

// ============================================================================
// Launch
// ============================================================================
extern "C" void kernel_launch(void* const* d_in, const int* in_sizes, int n_in,
                              void* d_out, int out_size)
{
    const float* x     = (const float*)d_in[0];
    const float* w_kqv = (const float*)d_in[1];
    const float* w_out = (const float*)d_in[2];
    const float* b_out = (const float*)d_in[3];
    float* out = (float*)d_out;

    __half *xhi, *xlo, *wkhi, *wklo, *wohi, *wolo, *ahi, *alo;
    cudaGetSymbolAddress((void**)&xhi, g_xhi);
    cudaGetSymbolAddress((void**)&xlo, g_xlo);
    cudaGetSymbolAddress((void**)&wkhi, g_wkhi);
    cudaGetSymbolAddress((void**)&wklo, g_wklo);
    cudaGetSymbolAddress((void**)&wohi, g_wohi);
    cudaGetSymbolAddress((void**)&wolo, g_wolo);
    cudaGetSymbolAddress((void**)&ahi, g_ahi);
    cudaGetSymbolAddress((void**)&alo, g_alo);

    cudaFuncSetAttribute(attn_mma,
                         cudaFuncAttributeMaxDynamicSharedMemorySize, ATTN_SMEM);
    cudaFuncSetAttribute(hgemm<0>,
                         cudaFuncAttributeMaxDynamicSharedMemorySize, G_SMEM);
    cudaFuncSetAttribute(hgemm<1>,
                         cudaFuncAttributeMaxDynamicSharedMemorySize, G_SMEM);

    // 0) split fp32 -> fp16 hi/lo
    split_kernel<<<512, 256>>>((const float4*)x, (uint2*)xhi, (uint2*)xlo,
                               ROWS_ * C_ / 4);
    split_kernel<<<192, 256>>>((const float4*)w_kqv, (uint2*)wkhi, (uint2*)wklo,
                               C_ * THREE_C / 4);
    split_kernel<<<64, 256>>>((const float4*)w_out, (uint2*)wohi, (uint2*)wolo,
                              C_ * C_ / 4);

    // 1) QKV GEMM (HMMA, split epilogue -> g_{k,q,v}{hi,lo})
    hgemm<1><<<dim3(THREE_C / 64, ROWS_ / 128), 256, G_SMEM>>>(
        xhi, xlo, wkhi, wklo, nullptr, nullptr, THREE_C);

    // 2) attention (mma.sync flash) -> g_a{hi,lo}
    attn_mma<<<B_ * H_ * (L_ / 128), 256, ATTN_SMEM>>>();

    // 3) out = attn @ w_out + bias (HMMA)
    hgemm<0><<<dim3(C_ / 64, ROWS_ / 128), 256, G_SMEM>>>(
        ahi, alo, wohi, wolo, b_out, out, C_);
}

// round 7
// speedup vs baseline: 3.2772x; 1.0958x over previous
#include <cuda_runtime.h>
#include <cuda_fp16.h>
#include <cstdint>

#define B_ 2
#define L_ 4096
#define C_ 512
#define H_ 8
#define D_ 64
#define THREE_C 1536
#define ROWS_ (B_ * L_)

// fp16 hi/lo split buffers
static __device__ __half g_xhi[(size_t)ROWS_ * C_];
static __device__ __half g_xlo[(size_t)ROWS_ * C_];
static __device__ __half g_wkhi[(size_t)C_ * THREE_C];
static __device__ __half g_wklo[(size_t)C_ * THREE_C];
static __device__ __half g_wohi[(size_t)C_ * C_];
static __device__ __half g_wolo[(size_t)C_ * C_];
static __device__ __half g_khi[(size_t)ROWS_ * C_];
static __device__ __half g_klo[(size_t)ROWS_ * C_];
static __device__ __half g_qhi[(size_t)ROWS_ * C_];   // pre-scaled by sqrt(512)*log2(e)
static __device__ __half g_qlo[(size_t)ROWS_ * C_];
static __device__ __half g_vhi[(size_t)ROWS_ * C_];
static __device__ __half g_vlo[(size_t)ROWS_ * C_];   // written, no longer read by attn
static __device__ __half g_ahi[(size_t)ROWS_ * C_];
static __device__ __half g_alo[(size_t)ROWS_ * C_];

#define QSCALE 32.644462410f   // sqrt(512) * log2(e)

// ============================================================================
// Small PTX helpers
// ============================================================================
__device__ __forceinline__ uint32_t smem_u32(const void* p) {
    uint32_t a;
    asm("{ .reg .u64 t; cvta.to.shared.u64 t, %1; cvt.u32.u64 %0, t; }"
        : "=r"(a) : "l"(p));
    return a;
}
#define CP16(dst, src) \
    asm volatile("cp.async.cg.shared.global [%0], [%1], 16;" :: "r"(dst), "l"(src))
#define CP_COMMIT() asm volatile("cp.async.commit_group;" ::: "memory")
#define CP_WAIT(n)  asm volatile("cp.async.wait_group %0;" :: "n"(n) : "memory")

__device__ __forceinline__ uint4 ldsm4(uint32_t addr) {
    uint4 v;
    asm volatile("ldmatrix.sync.aligned.m8n8.x4.shared.b16 {%0,%1,%2,%3}, [%4];"
                 : "=r"(v.x), "=r"(v.y), "=r"(v.z), "=r"(v.w) : "r"(addr));
    return v;
}
__device__ __forceinline__ uint4 ldsm4t(uint32_t addr) {
    uint4 v;
    asm volatile("ldmatrix.sync.aligned.m8n8.x4.trans.shared.b16 {%0,%1,%2,%3}, [%4];"
                 : "=r"(v.x), "=r"(v.y), "=r"(v.z), "=r"(v.w) : "r"(addr));
    return v;
}
__device__ __forceinline__ void mma16816(float* c, uint32_t a0, uint32_t a1,
                                         uint32_t a2, uint32_t a3,
                                         uint32_t b0, uint32_t b1) {
    asm volatile(
        "mma.sync.aligned.m16n8k16.row.col.f32.f16.f16.f32 "
        "{%0,%1,%2,%3}, {%4,%5,%6,%7}, {%8,%9}, {%0,%1,%2,%3};"
        : "+f"(c[0]), "+f"(c[1]), "+f"(c[2]), "+f"(c[3])
        : "r"(a0), "r"(a1), "r"(a2), "r"(a3), "r"(b0), "r"(b1));
}

// MUFU-free exp2 (deg-4: rel err ~4e-5 on [-0.5,0.5], well under fp16 P rounding)
__device__ __forceinline__ float exp2_fast(float d) {
    d = fmaxf(d, -80.f);
    float t = d + 12582912.f;
    float f = d - (t - 12582912.f);
    float p = 9.61812911e-3f;
    p = fmaf(p, f, 5.55041087e-2f);
    p = fmaf(p, f, 2.40226507e-1f);
    p = fmaf(p, f, 6.93147181e-1f);
    p = fmaf(p, f, 1.0f);
    return __int_as_float(__float_as_int(p) +
                          (int)((uint32_t)__float_as_int(t) << 23));
}

// ============================================================================
// fp32 -> fp16 hi/lo split
// ============================================================================
__global__ void split_kernel(const float4* __restrict__ src,
                             uint2* __restrict__ hi, uint2* __restrict__ lo,
                             int n4)
{
    for (int i = blockIdx.x * blockDim.x + threadIdx.x; i < n4;
         i += gridDim.x * blockDim.x) {
        float4 v = src[i];
        __half2 h0 = __floats2half2_rn(v.x, v.y);
        __half2 h1 = __floats2half2_rn(v.z, v.w);
        float2 f0 = __half22float2(h0), f1 = __half22float2(h1);
        __half2 l0 = __floats2half2_rn(v.x - f0.x, v.y - f0.y);
        __half2 l1 = __floats2half2_rn(v.z - f1.x, v.w - f1.y);
        hi[i] = make_uint2(*(uint32_t*)&h0, *(uint32_t*)&h1);
        lo[i] = make_uint2(*(uint32_t*)&l0, *(uint32_t*)&l1);
    }
}

// ============================================================================
// HMMA GEMM: 512 threads, BM=256, BN=64, BK=64, 16 warps (16 rows each).
// 3-chain fp16 split. MODE 0: fp32 out + bias. MODE 1: kqv split epilogue.
// ============================================================================
#define RSTR 144
#define GA_HI 0
#define GA_LO (256 * RSTR)
#define GB_HI (2 * 256 * RSTR)
#define GB_LO (2 * 256 * RSTR + 64 * RSTR)
#define G_STG_SZ (2 * 256 * RSTR + 2 * 64 * RSTR)   // 92160
#define G_SMEM (2 * G_STG_SZ)                        // 184320

template <int MODE>
__global__ void __launch_bounds__(512) hgemm(
    const __half* __restrict__ Ahi, const __half* __restrict__ Alo,
    const __half* __restrict__ Bhi, const __half* __restrict__ Blo,
    const float* __restrict__ bias, float* __restrict__ out, int N)
{
    extern __shared__ char smem[];
    const uint32_t sb = smem_u32(smem);
    const int tid = threadIdx.x;
    const int lane = tid & 31;
    const int wid = tid >> 5;
    const int bm = blockIdx.y * 256;
    const int bn = blockIdx.x * 64;

    auto issue_stage = [&](int stage, int k0) {
        const uint32_t stg = sb + stage * G_STG_SZ;
        // A tiles: 256 rows x 8 chunks (hi + lo)
#pragma unroll
        for (int k = 0; k < 4; ++k) {
            int idx = tid + k * 512;            // 0..2047
            int r = idx >> 3, c = idx & 7;
            CP16(stg + GA_HI + r * RSTR + c * 16,
                 Ahi + (size_t)(bm + r) * C_ + k0 + c * 8);
            CP16(stg + GA_LO + r * RSTR + c * 16,
                 Alo + (size_t)(bm + r) * C_ + k0 + c * 8);
        }
        // B tiles: 64 k-rows x 8 chunks (hi + lo)
        {
            int r = tid >> 3, c = tid & 7;      // 0..511
            CP16(stg + GB_HI + r * RSTR + c * 16,
                 Bhi + (size_t)(k0 + r) * N + bn + c * 8);
            CP16(stg + GB_LO + r * RSTR + c * 16,
                 Blo + (size_t)(k0 + r) * N + bn + c * 8);
        }
    };
    issue_stage(0, 0);
    CP_COMMIT();

    float acc[8][4];
#pragma unroll
    for (int nb = 0; nb < 8; ++nb)
#pragma unroll
        for (int j = 0; j < 4; ++j) acc[nb][j] = 0.f;

    const int qr0 = wid * 16;
    const uint32_t a_row_off =
        (uint32_t)((qr0 + (lane & 7) + ((lane >> 3) & 1) * 8) * RSTR + (lane >> 4) * 16);

    for (int kt = 0; kt < 8; ++kt) {
        if (kt + 1 < 8) {
            issue_stage((kt + 1) & 1, (kt + 1) * 64);
            CP_COMMIT();
            CP_WAIT(1);
        } else {
            CP_WAIT(0);
        }
        __syncthreads();

        const uint32_t stg = sb + (kt & 1) * G_STG_SZ;
#pragma unroll
        for (int chain = 0; chain < 3; ++chain) {
            const uint32_t abase = stg + (chain == 2 ? GA_LO : GA_HI) + a_row_off;
            const uint32_t bbase = stg + (chain == 1 ? GB_LO : GB_HI) + lane * RSTR;
            uint4 af[4];
#pragma unroll
            for (int kb = 0; kb < 4; ++kb)
                af[kb] = ldsm4(abase + kb * 32);
#pragma unroll
            for (int nb = 0; nb < 8; ++nb) {
#pragma unroll
                for (int kbp = 0; kbp < 2; ++kbp) {
                    uint4 bb = ldsm4t(bbase + kbp * 32 * RSTR + nb * 16);
                    mma16816(acc[nb], af[2 * kbp].x, af[2 * kbp].y,
                             af[2 * kbp].z, af[2 * kbp].w, bb.x, bb.y);
                    mma16816(acc[nb], af[2 * kbp + 1].x, af[2 * kbp + 1].y,
                             af[2 * kbp + 1].z, af[2 * kbp + 1].w, bb.z, bb.w);
                }
            }
        }
        __syncthreads();
    }

    // ---------------- epilogue ----------------
    const int row0 = bm + qr0 + (lane >> 2);
    if (MODE == 0) {
#pragma unroll
        for (int nb = 0; nb < 8; ++nb) {
            int col = bn + nb * 8 + 2 * (lane & 3);
            float2 b2 = *(const float2*)(bias + col);
            *(float2*)(out + (size_t)row0 * C_ + col) =
                make_float2(acc[nb][0] + b2.x, acc[nb][1] + b2.y);
            *(float2*)(out + (size_t)(row0 + 8) * C_ + col) =
                make_float2(acc[nb][2] + b2.x, acc[nb][3] + b2.y);
        }
    } else {
        const int chunk = bn >> 9;              // 0:k 1:q 2:v
        __half* hiB = chunk == 0 ? g_khi : (chunk == 1 ? g_qhi : g_vhi);
        __half* loB = chunk == 0 ? g_klo : (chunk == 1 ? g_qlo : g_vlo);
        const float sc = (chunk == 1) ? QSCALE : 1.f;
#pragma unroll
        for (int nb = 0; nb < 8; ++nb) {
            int lc = (bn & 511) + nb * 8 + 2 * (lane & 3);
#pragma unroll
            for (int half_ : {0, 1}) {
                int row = row0 + half_ * 8;
                float v0 = acc[nb][2 * half_] * sc;
                float v1 = acc[nb][2 * half_ + 1] * sc;
                __half2 h = __floats2half2_rn(v0, v1);
                float2 hf = __half22float2(h);
                __half2 l = __floats2half2_rn(v0 - hf.x, v1 - hf.y);
                *(uint32_t*)(hiB + (size_t)row * C_ + lc) = *(uint32_t*)&h;
                *(uint32_t*)(loB + (size_t)row * C_ + lc) = *(uint32_t*)&l;
            }
        }
    }
}

// ============================================================================
// Attention: mma.sync flash. 4 HMMA chains (3 S + Vhi only).
// ============================================================================
#define QHI_OFF 0
#define QLO_OFF (128 * RSTR)
#define STG_OFF (2 * 128 * RSTR)
#define TSZ (64 * RSTR)
#define KHI_SUB 0
#define KLO_SUB TSZ
#define VHI_SUB (2 * TSZ)
#define STG_SZ (3 * TSZ)                   // 27648
#define ATTN_SMEM (STG_OFF + 2 * STG_SZ)   // 92160 B

__global__ void __launch_bounds__(256) attn_mma()
{
    extern __shared__ char smem[];
    const uint32_t sb = smem_u32(smem);
    const int tid = threadIdx.x;
    const int lane = tid & 31;
    const int wid = tid >> 5;

    const int qt = blockIdx.x & 31;
    const int h = (blockIdx.x >> 5) & 7;
    const int b = blockIdx.x >> 8;

    const size_t bL = (size_t)b * L_;
    const int hc = h * D_;

    {
        const __half* qs[2] = {g_qhi, g_qlo};
#pragma unroll
        for (int k = 0; k < 8; ++k) {
            int idx = tid + k * 256;
            int buf = idx >> 10;
            int r = (idx >> 3) & 127;
            int c = idx & 7;
            const __half* src = qs[buf] + (bL + qt * 128 + r) * C_ + hc + c * 8;
            CP16(sb + (buf ? QLO_OFF : QHI_OFF) + r * RSTR + c * 16, src);
        }
    }
    const __half* kvsrc[3] = {g_khi, g_klo, g_vhi};
    auto issue_stage = [&](int stage, int kt) {
        const uint32_t stg = sb + STG_OFF + stage * STG_SZ;
#pragma unroll
        for (int s = 0; s < 3; ++s) {
#pragma unroll
            for (int k = 0; k < 2; ++k) {
                int idx = tid + k * 256;
                int r = idx >> 3;
                int c = idx & 7;
                const __half* src = kvsrc[s] + (bL + kt * 64 + r) * C_ + hc + c * 8;
                CP16(stg + s * TSZ + r * RSTR + c * 16, src);
            }
        }
    };
    issue_stage(0, 0);
    CP_COMMIT();

    float Oc[8][4];
#pragma unroll
    for (int nb = 0; nb < 8; ++nb)
#pragma unroll
        for (int j = 0; j < 4; ++j) Oc[nb][j] = 0.f;
    float m0 = -1e30f, m1 = -1e30f, rs0 = 0.f, rs1 = 0.f;

    const int qr0 = wid * 16;
    const uint32_t q_row_off =
        (uint32_t)((qr0 + (lane & 7) + ((lane >> 3) & 1) * 8) * RSTR + (lane >> 4) * 16);

    for (int kt = 0; kt < L_ / 64; ++kt) {
        if (kt + 1 < L_ / 64) {
            issue_stage((kt + 1) & 1, kt + 1);
            CP_COMMIT();
            CP_WAIT(1);
        } else {
            CP_WAIT(0);
        }
        __syncthreads();

        const uint32_t stg = sb + STG_OFF + (kt & 1) * STG_SZ;

        float Sc[8][4];
#pragma unroll
        for (int nb = 0; nb < 8; ++nb)
#pragma unroll
            for (int j = 0; j < 4; ++j) Sc[nb][j] = 0.f;

#pragma unroll
        for (int chain = 0; chain < 3; ++chain) {
            const uint32_t qbase = sb + (chain == 2 ? QLO_OFF : QHI_OFF) + q_row_off;
            const uint32_t kbase = stg + (chain == 1 ? KLO_SUB : KHI_SUB);
            uint4 qf[4];
#pragma unroll
            for (int kb = 0; kb < 4; ++kb)
                qf[kb] = ldsm4(qbase + kb * 32);
            const uint32_t krow = kbase + (uint32_t)(((lane & 7)) * RSTR + (lane >> 3) * 16);
#pragma unroll
            for (int nb = 0; nb < 8; ++nb) {
                const uint32_t ka = krow + nb * 8 * RSTR;
#pragma unroll
                for (int kbp = 0; kbp < 2; ++kbp) {
                    uint4 bb = ldsm4(ka + kbp * 64);
                    mma16816(Sc[nb], qf[2 * kbp].x, qf[2 * kbp].y,
                             qf[2 * kbp].z, qf[2 * kbp].w, bb.x, bb.y);
                    mma16816(Sc[nb], qf[2 * kbp + 1].x, qf[2 * kbp + 1].y,
                             qf[2 * kbp + 1].z, qf[2 * kbp + 1].w, bb.z, bb.w);
                }
            }
        }

        float t0 = -1e30f, t1 = -1e30f;
#pragma unroll
        for (int nb = 0; nb < 8; ++nb) {
            t0 = fmaxf(t0, fmaxf(Sc[nb][0], Sc[nb][1]));
            t1 = fmaxf(t1, fmaxf(Sc[nb][2], Sc[nb][3]));
        }
        t0 = fmaxf(t0, __shfl_xor_sync(0xFFFFFFFFu, t0, 1));
        t0 = fmaxf(t0, __shfl_xor_sync(0xFFFFFFFFu, t0, 2));
        t1 = fmaxf(t1, __shfl_xor_sync(0xFFFFFFFFu, t1, 1));
        t1 = fmaxf(t1, __shfl_xor_sync(0xFFFFFFFFu, t1, 2));
        const float mn0 = fmaxf(m0, t0), mn1 = fmaxf(m1, t1);
        const float corr0 = exp2_fast(m0 - mn0), corr1 = exp2_fast(m1 - mn1);
        m0 = mn0; m1 = mn1;

        uint32_t pA[4][4];
        float ps0 = 0.f, ps1 = 0.f;
#pragma unroll
        for (int nb = 0; nb < 8; ++nb) {
            float p00 = exp2_fast(Sc[nb][0] - m0);
            float p01 = exp2_fast(Sc[nb][1] - m0);
            float p10 = exp2_fast(Sc[nb][2] - m1);
            float p11 = exp2_fast(Sc[nb][3] - m1);
            __half2 hlo = __floats2half2_rn(p00, p01);
            __half2 hhi = __floats2half2_rn(p10, p11);
            float2 flo = __half22float2(hlo);
            float2 fhi = __half22float2(hhi);
            ps0 += flo.x + flo.y;
            ps1 += fhi.x + fhi.y;
            uint32_t lo2 = *reinterpret_cast<uint32_t*>(&hlo);
            uint32_t hi2 = *reinterpret_cast<uint32_t*>(&hhi);
            if (nb & 1) { pA[nb >> 1][2] = lo2; pA[nb >> 1][3] = hi2; }
            else        { pA[nb >> 1][0] = lo2; pA[nb >> 1][1] = hi2; }
        }
        ps0 += __shfl_xor_sync(0xFFFFFFFFu, ps0, 1);
        ps0 += __shfl_xor_sync(0xFFFFFFFFu, ps0, 2);
        ps1 += __shfl_xor_sync(0xFFFFFFFFu, ps1, 1);
        ps1 += __shfl_xor_sync(0xFFFFFFFFu, ps1, 2);
        rs0 = rs0 * corr0 + ps0;
        rs1 = rs1 * corr1 + ps1;
#pragma unroll
        for (int nb = 0; nb < 8; ++nb) {
            Oc[nb][0] *= corr0; Oc[nb][1] *= corr0;
            Oc[nb][2] *= corr1; Oc[nb][3] *= corr1;
        }

        // O += P Vhi (single chain)
        {
            const uint32_t vbase = stg + VHI_SUB + lane * RSTR;
#pragma unroll
            for (int nb = 0; nb < 8; ++nb) {
#pragma unroll
                for (int kbp = 0; kbp < 2; ++kbp) {
                    uint4 vv = ldsm4t(vbase + kbp * 32 * RSTR + nb * 16);
                    mma16816(Oc[nb], pA[2 * kbp][0], pA[2 * kbp][1],
                             pA[2 * kbp][2], pA[2 * kbp][3], vv.x, vv.y);
                    mma16816(Oc[nb], pA[2 * kbp + 1][0], pA[2 * kbp + 1][1],
                             pA[2 * kbp + 1][2], pA[2 * kbp + 1][3], vv.z, vv.w);
                }
            }
        }
        __syncthreads();
    }

    // ---------- epilogue: write O as fp16 hi/lo ----------
    const float inv0 = 1.f / rs0, inv1 = 1.f / rs1;
    const int r = qt * 128 + qr0 + (lane >> 2);
    const int colb = hc + 2 * (lane & 3);
#pragma unroll
    for (int nb = 0; nb < 8; ++nb) {
        float a0 = Oc[nb][0] * inv0, a1 = Oc[nb][1] * inv0;
        float b0 = Oc[nb][2] * inv1, b1 = Oc[nb][3] * inv1;
        __half2 h0 = __floats2half2_rn(a0, a1);
        __half2 h1 = __floats2half2_rn(b0, b1);
        float2 f0 = __half22float2(h0), f1 = __half22float2(h1);
        __half2 l0 = __floats2half2_rn(a0 - f0.x, a1 - f0.y);
        __half2 l1 = __floats2half2_rn(b0 - f1.x, b1 - f1.y);
        size_t base0 = (bL + r) * C_ + colb + nb * 8;
        size_t base1 = (bL + r + 8) * C_ + colb + nb * 8;
        *(uint32_t*)(g_ahi + base0) = *(uint32_t*)&h0;
        *(uint32_t*)(g_alo + base0) = *(uint32_t*)&l0;
        *(uint32_t*)(g_ahi + base1) = *(uint32_t*)&h1;
        *(uint32_t*)(g_alo + base1) = *(uint32_t*)&l1;
    }
}

// ============================================================================
// Launch
// ============================================================================
extern "C" void kernel_launch(void* const* d_in, const int* in_sizes, int n_in,
                              void* d_out, int out_size)
{
    const float* x     = (const float*)d_in[0];
    const float* w_kqv = (const float*)d_in[1];
    const float* w_out = (const float*)d_in[2];
    const float* b_out = (const float*)d_in[3];
    float* out = (float*)d_out;

    __half *xhi, *xlo, *wkhi, *wklo, *wohi, *wolo, *ahi, *alo;
    cudaGetSymbolAddress((void**)&xhi, g_xhi);
    cudaGetSymbolAddress((void**)&xlo, g_xlo);
    cudaGetSymbolAddress((void**)&wkhi, g_wkhi);
    cudaGetSymbolAddress((void**)&wklo, g_wklo);
    cudaGetSymbolAddress((void**)&wohi, g_wohi);
    cudaGetSymbolAddress((void**)&wolo, g_wolo);
    cudaGetSymbolAddress((void**)&ahi, g_ahi);
    cudaGetSymbolAddress((void**)&alo, g_alo);

    cudaFuncSetAttribute(attn_mma,
                         cudaFuncAttributeMaxDynamicSharedMemorySize, ATTN_SMEM);
    cudaFuncSetAttribute(hgemm<0>,
                         cudaFuncAttributeMaxDynamicSharedMemorySize, G_SMEM);
    cudaFuncSetAttribute(hgemm<1>,
                         cudaFuncAttributeMaxDynamicSharedMemorySize, G_SMEM);

    // 0) split fp32 -> fp16 hi/lo
    split_kernel<<<512, 256>>>((const float4*)x, (uint2*)xhi, (uint2*)xlo,
                               ROWS_ * C_ / 4);
    split_kernel<<<192, 256>>>((const float4*)w_kqv, (uint2*)wkhi, (uint2*)wklo,
                               C_ * THREE_C / 4);
    split_kernel<<<64, 256>>>((const float4*)w_out, (uint2*)wohi, (uint2*)wolo,
                              C_ * C_ / 4);

    // 1) QKV GEMM (HMMA, split epilogue -> g_{k,q,v}{hi,lo})
    hgemm<1><<<dim3(THREE_C / 64, ROWS_ / 256), 512, G_SMEM>>>(
        xhi, xlo, wkhi, wklo, nullptr, nullptr, THREE_C);

    // 2) attention (mma.sync flash, 4 chains) -> g_a{hi,lo}
    attn_mma<<<B_ * H_ * (L_ / 128), 256, ATTN_SMEM>>>();

    // 3) out = attn @ w_out + bias (HMMA)
    hgemm<0><<<dim3(C_ / 64, ROWS_ / 256), 512, G_SMEM>>>(
        ahi, alo, wohi, wolo, b_out, out, C_);
}